// round 1
// baseline (speedup 1.0000x reference)
#include <cuda_runtime.h>
#include <math.h>
#include <stdint.h>

#define N_NODES 12000
#define N_EDGES 384000
#define FIN_    128
#define DD      64
#define BUF     (N_NODES * DD)   // 768000

// Scratch (no allocation allowed): 7 float buffers + dis + int CSR + BN sums
__device__ float  g_fsc[7 * BUF + N_NODES];
__device__ int    g_isc[N_NODES + (N_NODES + 1) + N_NODES + N_EDGES];
__device__ double g_sums[128];

// ---------------- graph prep ----------------
__global__ void zero_cnt_kernel(int* cnt) {
    int i = blockIdx.x * 256 + threadIdx.x;
    if (i < N_NODES) cnt[i] = 0;
}

__global__ void hist_kernel(const int* __restrict__ dst, int* cnt) {
    int i = blockIdx.x * 256 + threadIdx.x;   // grid exact: 1500*256
    atomicAdd(&cnt[dst[i]], 1);
}

__global__ void scan_kernel(const int* __restrict__ cnt, int* __restrict__ off,
                            int* __restrict__ cur, float* __restrict__ dis) {
    __shared__ int part[1024];
    const int C = 12;                        // 1024*12 = 12288 >= 12000
    int tid = threadIdx.x;
    int base = tid * C;
    int loc[C];
    int s = 0;
#pragma unroll
    for (int j = 0; j < C; j++) {
        int i = base + j;
        int v = (i < N_NODES) ? cnt[i] : 0;
        loc[j] = v; s += v;
    }
    part[tid] = s;
    __syncthreads();
    for (int d = 1; d < 1024; d <<= 1) {
        int v = 0;
        if (tid >= d) v = part[tid - d];
        __syncthreads();
        part[tid] += v;
        __syncthreads();
    }
    int run = (tid == 0) ? 0 : part[tid - 1];
#pragma unroll
    for (int j = 0; j < C; j++) {
        int i = base + j;
        if (i < N_NODES) {
            off[i] = run; cur[i] = run;
            dis[i] = rsqrtf((float)(loc[j] + 1));   // self-loop => deg+1
            run += loc[j];
        }
    }
    if (tid == 1023) off[N_NODES] = run;
}

__global__ void fill_kernel(const int* __restrict__ src, const int* __restrict__ dst,
                            int* cur, int* __restrict__ csr) {
    int i = blockIdx.x * 256 + threadIdx.x;
    int p = atomicAdd(&cur[dst[i]], 1);
    csr[p] = src[i];
}

// ---------------- small GEMM: Y[N, NOUT] = epi(X[N,FIN] @ W[FIN,NOUT]) -------
// EPI 0: Y = dis[row] * (X@W)           (GCN pre-scale, bias added in gather)
// EPI 1: Y = leaky_relu(X@W + bias)
// EPI 2: Y = X@W + bias
template <int FIN, int NOUT, int EPI>
__global__ void gemm_kernel(const float* __restrict__ X, const float* __restrict__ W,
                            const float* __restrict__ aux, float* __restrict__ Y) {
    __shared__ float xs[16 * FIN];
    int tid = threadIdx.x;
    int rowbase = blockIdx.x * 16;           // 750 blocks exactly
    const float4* Xg = (const float4*)(X + (size_t)rowbase * FIN);
    float4* xs4 = (float4*)xs;
#pragma unroll
    for (int u = tid; u < 16 * FIN / 4; u += 256) xs4[u] = Xg[u];
    __syncthreads();

    const int LANES = 256 / NOUT;            // 4 (NOUT=64) or 2 (NOUT=128)
    const int RPT   = 16 / LANES;            // 4 or 8
    int col = tid % NOUT;
    int rl  = tid / NOUT;
    float acc[RPT];
#pragma unroll
    for (int r = 0; r < RPT; r++) acc[r] = 0.f;

#pragma unroll 4
    for (int k = 0; k < FIN; k++) {
        float w = __ldg(&W[k * NOUT + col]);
#pragma unroll
        for (int r = 0; r < RPT; r++)
            acc[r] += xs[(rl * RPT + r) * FIN + k] * w;
    }
#pragma unroll
    for (int r = 0; r < RPT; r++) {
        int row = rowbase + rl * RPT + r;
        float v = acc[r];
        if (EPI == 0) {
            v *= aux[row];
        } else {
            v += aux[col];
            if (EPI == 1) v = (v > 0.f) ? v : 0.01f * v;
        }
        Y[(size_t)row * NOUT + col] = v;
    }
}

// ------------- gather + bias + sigmoid (one warp per node, float2/thread) ----
__global__ void gather_sig_kernel(const float* __restrict__ hs, const float* __restrict__ dis,
                                  const int* __restrict__ off, const int* __restrict__ csr,
                                  const float* __restrict__ bias, float* __restrict__ sbuf) {
    int warp = (blockIdx.x * 256 + threadIdx.x) >> 5;   // 12000 warps exactly
    int lane = threadIdx.x & 31;
    const float2* h2 = (const float2*)hs;
    float2 acc = h2[(size_t)warp * 32 + lane];          // self term (hs already dis-scaled)
    int e0 = off[warp], e1 = off[warp + 1];
    for (int e = e0; e < e1; e++) {
        int s = __ldg(&csr[e]);
        float2 v = h2[(size_t)s * 32 + lane];
        acc.x += v.x; acc.y += v.y;
    }
    float dd = dis[warp];
    float2 bb = ((const float2*)bias)[lane];
    float vx = dd * acc.x + bb.x;
    float vy = dd * acc.y + bb.y;
    vx = 1.f / (1.f + __expf(-vx));
    vy = 1.f / (1.f + __expf(-vy));
    ((float2*)sbuf)[(size_t)warp * 32 + lane] = make_float2(vx, vy);
}

// ---------------- BatchNorm (training stats), double accumulation -----------
__global__ void zero_stats_kernel(double* sums) { sums[threadIdx.x] = 0.0; }

__global__ void stats_kernel(const float* __restrict__ sbuf, double* __restrict__ sums) {
    int tid = threadIdx.x;
    int c = tid & 63, rg = tid >> 6;
    double s = 0.0, s2 = 0.0;
    for (int row = blockIdx.x * 4 + rg; row < N_NODES; row += 64 * 4) {
        float v = sbuf[(size_t)row * 64 + c];
        s += v; s2 += (double)v * (double)v;
    }
    __shared__ double sh[256], sh2[256];
    sh[tid] = s; sh2[tid] = s2;
    __syncthreads();
    if (rg == 0) {
        s  = sh[tid]  + sh[tid + 64]  + sh[tid + 128]  + sh[tid + 192];
        s2 = sh2[tid] + sh2[tid + 64] + sh2[tid + 128] + sh2[tid + 192];
        atomicAdd(&sums[c], s);
        atomicAdd(&sums[64 + c], s2);
    }
}

__global__ void bn_apply_kernel(const float* __restrict__ sbuf, const double* __restrict__ sums,
                                const float* __restrict__ gamma, const float* __restrict__ beta,
                                float* __restrict__ out) {
    int idx = blockIdx.x * 256 + threadIdx.x;   // 3000*256 = 768000 exact
    int c = idx & 63;
    double mu  = sums[c] * (1.0 / N_NODES);
    double var = sums[64 + c] * (1.0 / N_NODES) - mu * mu;
    float inv = rsqrtf((float)var + 1e-4f);
    out[idx] = (float)((double)sbuf[idx] - mu) * inv * gamma[c] + beta[c];
}

// ---------------- z = noise * exp(logstd) + mean ----------------------------
__global__ void z_kernel(const float* __restrict__ noise, const float* __restrict__ logstd,
                         const float* __restrict__ mean, float* __restrict__ z) {
    int idx = blockIdx.x * 256 + threadIdx.x;
    z[idx] = noise[idx] * expf(logstd[idx]) + mean[idx];
}

// ---------------- A_pred = sigmoid(z @ z^T), 128x128 tiles, 8x8/thread ------
__global__ void __launch_bounds__(256)
apred_kernel(const float* __restrict__ z, float* __restrict__ out) {
    extern __shared__ float sm[];
    float* As = sm;             // [64][128]  k-major
    float* Bs = sm + 64 * 128;  // [64][128]
    int tid = threadIdx.x;
    int row0 = blockIdx.y * 128, col0 = blockIdx.x * 128;

    // load tiles (k-major transpose in smem); zero-pad rows >= N
    for (int u = tid; u < 2048; u += 256) {
        int r = u & 127, k4 = u >> 7;
        int gr = row0 + r;
        float4 v = make_float4(0.f, 0.f, 0.f, 0.f);
        if (gr < N_NODES) v = *(const float4*)(z + (size_t)gr * 64 + k4 * 4);
        As[(k4 * 4 + 0) * 128 + r] = v.x;
        As[(k4 * 4 + 1) * 128 + r] = v.y;
        As[(k4 * 4 + 2) * 128 + r] = v.z;
        As[(k4 * 4 + 3) * 128 + r] = v.w;
        int gc = col0 + r;
        float4 w = make_float4(0.f, 0.f, 0.f, 0.f);
        if (gc < N_NODES) w = *(const float4*)(z + (size_t)gc * 64 + k4 * 4);
        Bs[(k4 * 4 + 0) * 128 + r] = w.x;
        Bs[(k4 * 4 + 1) * 128 + r] = w.y;
        Bs[(k4 * 4 + 2) * 128 + r] = w.z;
        Bs[(k4 * 4 + 3) * 128 + r] = w.w;
    }
    __syncthreads();

    int tx = tid & 15, ty = tid >> 4;
    float acc[8][8];
#pragma unroll
    for (int i = 0; i < 8; i++)
#pragma unroll
        for (int j = 0; j < 8; j++) acc[i][j] = 0.f;

#pragma unroll 8
    for (int k = 0; k < 64; k++) {
        float4 a0 = *(const float4*)(As + k * 128 + ty * 8);
        float4 a1 = *(const float4*)(As + k * 128 + ty * 8 + 4);
        float4 b0 = *(const float4*)(Bs + k * 128 + tx * 8);
        float4 b1 = *(const float4*)(Bs + k * 128 + tx * 8 + 4);
        float a[8] = {a0.x, a0.y, a0.z, a0.w, a1.x, a1.y, a1.z, a1.w};
        float b[8] = {b0.x, b0.y, b0.z, b0.w, b1.x, b1.y, b1.z, b1.w};
#pragma unroll
        for (int i = 0; i < 8; i++)
#pragma unroll
            for (int j = 0; j < 8; j++) acc[i][j] += a[i] * b[j];
    }

    int rbase = row0 + ty * 8;
    int cbase = col0 + tx * 8;
#pragma unroll
    for (int i = 0; i < 8; i++) {
        int r = rbase + i;
        if (r < N_NODES) {
            float* orow = out + (size_t)r * N_NODES;
#pragma unroll
            for (int j4 = 0; j4 < 2; j4++) {
                int c = cbase + j4 * 4;
                if (c < N_NODES) {   // N%4==0 and c%4==0 => full float4 valid
                    float4 v;
                    v.x = 1.f / (1.f + __expf(-acc[i][j4 * 4 + 0]));
                    v.y = 1.f / (1.f + __expf(-acc[i][j4 * 4 + 1]));
                    v.z = 1.f / (1.f + __expf(-acc[i][j4 * 4 + 2]));
                    v.w = 1.f / (1.f + __expf(-acc[i][j4 * 4 + 3]));
                    *(float4*)(orow + c) = v;
                }
            }
        }
    }
}

// ---------------- launch -----------------------------------------------------
extern "C" void kernel_launch(void* const* d_in, const int* in_sizes, int n_in,
                              void* d_out, int out_size) {
    const float* x     = (const float*)d_in[0];
    const int*   src   = (const int*)  d_in[1];
    const int*   dst   = (const int*)  d_in[2];
    const float* noise = (const float*)d_in[4];
    const float* W0  = (const float*)d_in[5];
    const float* b0  = (const float*)d_in[6];
    const float* g0  = (const float*)d_in[7];
    const float* be0 = (const float*)d_in[8];
    const float* Wm  = (const float*)d_in[9];
    const float* bm  = (const float*)d_in[10];
    const float* gm  = (const float*)d_in[11];
    const float* bem = (const float*)d_in[12];
    const float* Ws  = (const float*)d_in[13];
    const float* bs  = (const float*)d_in[14];
    const float* gs  = (const float*)d_in[15];
    const float* bes = (const float*)d_in[16];
    const float* Dw1 = (const float*)d_in[17];
    const float* Db1 = (const float*)d_in[18];
    const float* Dw2 = (const float*)d_in[19];
    const float* Db2 = (const float*)d_in[20];
    float* out = (float*)d_out;

    float* fsc; int* isc; double* sums;
    cudaGetSymbolAddress((void**)&fsc, g_fsc);
    cudaGetSymbolAddress((void**)&isc, g_isc);
    cudaGetSymbolAddress((void**)&sums, g_sums);

    float* HS   = fsc + 0 * BUF;
    float* SB   = fsc + 1 * BUF;
    float* HID  = fsc + 2 * BUF;
    float* MEAN = fsc + 3 * BUF;
    float* LOG  = fsc + 4 * BUF;
    float* Z    = fsc + 5 * BUF;
    float* H1   = fsc + 6 * BUF;
    float* DIS  = fsc + 7 * BUF;
    int* CNT = isc;
    int* OFF = CNT + N_NODES;
    int* CUR = OFF + N_NODES + 1;
    int* CSR = CUR + N_NODES;

    cudaFuncSetAttribute(apred_kernel, cudaFuncAttributeMaxDynamicSharedMemorySize, 65536);

    // graph prep
    zero_cnt_kernel<<<47, 256>>>(CNT);
    hist_kernel<<<1500, 256>>>(dst, CNT);
    scan_kernel<<<1, 1024>>>(CNT, OFF, CUR, DIS);
    fill_kernel<<<1500, 256>>>(src, dst, CUR, CSR);

    // layer 1: x(128) -> hidden(64)
    gemm_kernel<FIN_, DD, 0><<<750, 256>>>(x, W0, DIS, HS);
    gather_sig_kernel<<<1500, 256>>>(HS, DIS, OFF, CSR, b0, SB);
    zero_stats_kernel<<<1, 128>>>(sums);
    stats_kernel<<<64, 256>>>(SB, sums);
    bn_apply_kernel<<<3000, 256>>>(SB, sums, g0, be0, HID);

    // layer 2: hidden -> mean
    gemm_kernel<DD, DD, 0><<<750, 256>>>(HID, Wm, DIS, HS);
    gather_sig_kernel<<<1500, 256>>>(HS, DIS, OFF, CSR, bm, SB);
    zero_stats_kernel<<<1, 128>>>(sums);
    stats_kernel<<<64, 256>>>(SB, sums);
    bn_apply_kernel<<<3000, 256>>>(SB, sums, gm, bem, MEAN);

    // layer 3: hidden -> logstd
    gemm_kernel<DD, DD, 0><<<750, 256>>>(HID, Ws, DIS, HS);
    gather_sig_kernel<<<1500, 256>>>(HS, DIS, OFF, CSR, bs, SB);
    zero_stats_kernel<<<1, 128>>>(sums);
    stats_kernel<<<64, 256>>>(SB, sums);
    bn_apply_kernel<<<3000, 256>>>(SB, sums, gs, bes, LOG);

    // reparameterize
    z_kernel<<<3000, 256>>>(noise, LOG, MEAN, Z);

    // decoder MLP -> out[0 : 12000*128]
    gemm_kernel<DD, DD, 1><<<750, 256>>>(Z, Dw1, Db1, H1);
    gemm_kernel<DD, FIN_, 2><<<750, 256>>>(H1, Dw2, Db2, out);

    // A_pred -> out[12000*128 : ]
    dim3 grid((N_NODES + 127) / 128, (N_NODES + 127) / 128);
    apred_kernel<<<grid, 256, 65536>>>(Z, out + (size_t)N_NODES * FIN_);
}

// round 2
// speedup vs baseline: 2.5421x; 2.5421x over previous
#include <cuda_runtime.h>
#include <math.h>
#include <stdint.h>

#define N_NODES 12000
#define N_EDGES 384000
#define FIN_    128
#define DD      64
#define BUF     (N_NODES * DD)   // 768000

// Scratch (no allocation allowed): 7 float buffers + dis + int CSR + BN sums
__device__ float  g_fsc[7 * BUF + N_NODES];
__device__ int    g_isc[N_NODES + (N_NODES + 1) + N_NODES + N_EDGES];
__device__ double g_sums[128];

// ---------------- graph prep ----------------
__global__ void zero_cnt_kernel(int* cnt) {
    int i = blockIdx.x * 256 + threadIdx.x;
    if (i < N_NODES) cnt[i] = 0;
}

__global__ void hist_kernel(const int* __restrict__ dst, int* cnt) {
    int i = blockIdx.x * 256 + threadIdx.x;   // grid exact: 1500*256
    atomicAdd(&cnt[dst[i]], 1);
}

__global__ void scan_kernel(const int* __restrict__ cnt, int* __restrict__ off,
                            int* __restrict__ cur, float* __restrict__ dis) {
    __shared__ int part[1024];
    const int C = 12;                        // 1024*12 = 12288 >= 12000
    int tid = threadIdx.x;
    int base = tid * C;
    int loc[C];
    int s = 0;
#pragma unroll
    for (int j = 0; j < C; j++) {
        int i = base + j;
        int v = (i < N_NODES) ? cnt[i] : 0;
        loc[j] = v; s += v;
    }
    part[tid] = s;
    __syncthreads();
    for (int d = 1; d < 1024; d <<= 1) {
        int v = 0;
        if (tid >= d) v = part[tid - d];
        __syncthreads();
        part[tid] += v;
        __syncthreads();
    }
    int run = (tid == 0) ? 0 : part[tid - 1];
#pragma unroll
    for (int j = 0; j < C; j++) {
        int i = base + j;
        if (i < N_NODES) {
            off[i] = run; cur[i] = run;
            dis[i] = rsqrtf((float)(loc[j] + 1));   // self-loop => deg+1
            run += loc[j];
        }
    }
    if (tid == 1023) off[N_NODES] = run;
}

__global__ void fill_kernel(const int* __restrict__ src, const int* __restrict__ dst,
                            int* cur, int* __restrict__ csr) {
    int i = blockIdx.x * 256 + threadIdx.x;
    int p = atomicAdd(&cur[dst[i]], 1);
    csr[p] = src[i];
}

// ---------------- small GEMM: Y[N, NOUT] = epi(X[N,FIN] @ W[FIN,NOUT]) -------
// EPI 0: Y = dis[row] * (X@W)           (GCN pre-scale, bias added in gather)
// EPI 1: Y = leaky_relu(X@W + bias)
// EPI 2: Y = X@W + bias
template <int FIN, int NOUT, int EPI>
__global__ void gemm_kernel(const float* __restrict__ X, const float* __restrict__ W,
                            const float* __restrict__ aux, float* __restrict__ Y) {
    __shared__ float xs[16 * FIN];
    int tid = threadIdx.x;
    int rowbase = blockIdx.x * 16;           // 750 blocks exactly
    const float4* Xg = (const float4*)(X + (size_t)rowbase * FIN);
    float4* xs4 = (float4*)xs;
#pragma unroll
    for (int u = tid; u < 16 * FIN / 4; u += 256) xs4[u] = Xg[u];
    __syncthreads();

    const int LANES = 256 / NOUT;            // 4 (NOUT=64) or 2 (NOUT=128)
    const int RPT   = 16 / LANES;            // 4 or 8
    int col = tid % NOUT;
    int rl  = tid / NOUT;
    float acc[RPT];
#pragma unroll
    for (int r = 0; r < RPT; r++) acc[r] = 0.f;

#pragma unroll 4
    for (int k = 0; k < FIN; k++) {
        float w = __ldg(&W[k * NOUT + col]);
#pragma unroll
        for (int r = 0; r < RPT; r++)
            acc[r] += xs[(rl * RPT + r) * FIN + k] * w;
    }
#pragma unroll
    for (int r = 0; r < RPT; r++) {
        int row = rowbase + rl * RPT + r;
        float v = acc[r];
        if (EPI == 0) {
            v *= aux[row];
        } else {
            v += aux[col];
            if (EPI == 1) v = (v > 0.f) ? v : 0.01f * v;
        }
        Y[(size_t)row * NOUT + col] = v;
    }
}

// ------------- gather + bias + sigmoid (one warp per node, float2/thread) ----
__global__ void gather_sig_kernel(const float* __restrict__ hs, const float* __restrict__ dis,
                                  const int* __restrict__ off, const int* __restrict__ csr,
                                  const float* __restrict__ bias, float* __restrict__ sbuf) {
    int warp = (blockIdx.x * 256 + threadIdx.x) >> 5;   // 12000 warps exactly
    int lane = threadIdx.x & 31;
    const float2* h2 = (const float2*)hs;
    float2 acc = h2[(size_t)warp * 32 + lane];          // self term (hs already dis-scaled)
    int e0 = off[warp], e1 = off[warp + 1];
    for (int e = e0; e < e1; e++) {
        int s = __ldg(&csr[e]);
        float2 v = h2[(size_t)s * 32 + lane];
        acc.x += v.x; acc.y += v.y;
    }
    float dd = dis[warp];
    float2 bb = ((const float2*)bias)[lane];
    float vx = dd * acc.x + bb.x;
    float vy = dd * acc.y + bb.y;
    vx = __fdividef(1.f, 1.f + __expf(-vx));
    vy = __fdividef(1.f, 1.f + __expf(-vy));
    ((float2*)sbuf)[(size_t)warp * 32 + lane] = make_float2(vx, vy);
}

// ---------------- BatchNorm (training stats), double accumulation -----------
__global__ void zero_stats_kernel(double* sums) { sums[threadIdx.x] = 0.0; }

__global__ void stats_kernel(const float* __restrict__ sbuf, double* __restrict__ sums) {
    int tid = threadIdx.x;
    int c = tid & 63, rg = tid >> 6;
    double s = 0.0, s2 = 0.0;
    for (int row = blockIdx.x * 4 + rg; row < N_NODES; row += 64 * 4) {
        float v = sbuf[(size_t)row * 64 + c];
        s += v; s2 += (double)v * (double)v;
    }
    __shared__ double sh[256], sh2[256];
    sh[tid] = s; sh2[tid] = s2;
    __syncthreads();
    if (rg == 0) {
        s  = sh[tid]  + sh[tid + 64]  + sh[tid + 128]  + sh[tid + 192];
        s2 = sh2[tid] + sh2[tid + 64] + sh2[tid + 128] + sh2[tid + 192];
        atomicAdd(&sums[c], s);
        atomicAdd(&sums[64 + c], s2);
    }
}

__global__ void bn_apply_kernel(const float* __restrict__ sbuf, const double* __restrict__ sums,
                                const float* __restrict__ gamma, const float* __restrict__ beta,
                                float* __restrict__ out) {
    int idx = blockIdx.x * 256 + threadIdx.x;   // 3000*256 = 768000 exact
    int c = idx & 63;
    double mu  = sums[c] * (1.0 / N_NODES);
    double var = sums[64 + c] * (1.0 / N_NODES) - mu * mu;
    float inv = rsqrtf((float)var + 1e-4f);
    out[idx] = (float)((double)sbuf[idx] - mu) * inv * gamma[c] + beta[c];
}

// ---------------- z = noise * exp(logstd) + mean ----------------------------
__global__ void z_kernel(const float* __restrict__ noise, const float* __restrict__ logstd,
                         const float* __restrict__ mean, float* __restrict__ z) {
    int idx = blockIdx.x * 256 + threadIdx.x;
    z[idx] = noise[idx] * expf(logstd[idx]) + mean[idx];
}

// ------- A_pred = sigmoid(z @ z^T): SYMMETRIC, upper-tri blocks only --------
// 128x128 tiles, 8x8 per thread. Each off-diagonal block writes its tile AND
// the transposed tile (fire-and-forget strided float4 stores ride L1tex under
// the FFMA floor). Sigmoid computed once per element, via EX2+RCP.
__global__ void __launch_bounds__(256)
apred_kernel(const float* __restrict__ z, float* __restrict__ out) {
    int bi = blockIdx.y, bj = blockIdx.x;
    if (bj < bi) return;                     // lower triangle: nothing to do

    extern __shared__ float sm[];
    float* As = sm;             // [64][128]  k-major
    float* Bs = sm + 64 * 128;  // [64][128]
    int tid = threadIdx.x;
    int row0 = bi * 128, col0 = bj * 128;

    // load tiles (k-major transpose in smem); zero-pad rows >= N
    for (int u = tid; u < 2048; u += 256) {
        int r = u & 127, k4 = u >> 7;
        int gr = row0 + r;
        float4 v = make_float4(0.f, 0.f, 0.f, 0.f);
        if (gr < N_NODES) v = *(const float4*)(z + (size_t)gr * 64 + k4 * 4);
        As[(k4 * 4 + 0) * 128 + r] = v.x;
        As[(k4 * 4 + 1) * 128 + r] = v.y;
        As[(k4 * 4 + 2) * 128 + r] = v.z;
        As[(k4 * 4 + 3) * 128 + r] = v.w;
        int gc = col0 + r;
        float4 w = make_float4(0.f, 0.f, 0.f, 0.f);
        if (gc < N_NODES) w = *(const float4*)(z + (size_t)gc * 64 + k4 * 4);
        Bs[(k4 * 4 + 0) * 128 + r] = w.x;
        Bs[(k4 * 4 + 1) * 128 + r] = w.y;
        Bs[(k4 * 4 + 2) * 128 + r] = w.z;
        Bs[(k4 * 4 + 3) * 128 + r] = w.w;
    }
    __syncthreads();

    int tx = tid & 15, ty = tid >> 4;
    float acc[8][8];
#pragma unroll
    for (int i = 0; i < 8; i++)
#pragma unroll
        for (int j = 0; j < 8; j++) acc[i][j] = 0.f;

#pragma unroll 8
    for (int k = 0; k < 64; k++) {
        float4 a0 = *(const float4*)(As + k * 128 + ty * 8);
        float4 a1 = *(const float4*)(As + k * 128 + ty * 8 + 4);
        float4 b0 = *(const float4*)(Bs + k * 128 + tx * 8);
        float4 b1 = *(const float4*)(Bs + k * 128 + tx * 8 + 4);
        float a[8] = {a0.x, a0.y, a0.z, a0.w, a1.x, a1.y, a1.z, a1.w};
        float b[8] = {b0.x, b0.y, b0.z, b0.w, b1.x, b1.y, b1.z, b1.w};
#pragma unroll
        for (int i = 0; i < 8; i++)
#pragma unroll
            for (int j = 0; j < 8; j++) acc[i][j] += a[i] * b[j];
    }

    // sigmoid once, in registers
#pragma unroll
    for (int i = 0; i < 8; i++)
#pragma unroll
        for (int j = 0; j < 8; j++)
            acc[i][j] = __fdividef(1.f, 1.f + __expf(-acc[i][j]));

    int rbase = row0 + ty * 8;
    int cbase = col0 + tx * 8;

    // normal tile store (coalesced float4 along columns)
#pragma unroll
    for (int i = 0; i < 8; i++) {
        int r = rbase + i;
        if (r < N_NODES) {
            float* orow = out + (size_t)r * N_NODES;
#pragma unroll
            for (int j4 = 0; j4 < 2; j4++) {
                int c = cbase + j4 * 4;
                if (c < N_NODES) {
                    *(float4*)(orow + c) = make_float4(acc[i][j4 * 4 + 0], acc[i][j4 * 4 + 1],
                                                       acc[i][j4 * 4 + 2], acc[i][j4 * 4 + 3]);
                }
            }
        }
    }

    // transposed tile store (off-diagonal only). rows here are the original
    // columns c; float4 runs along the original row index r. bi < bj <= 93
    // implies bi <= 92, so r = rbase+i <= 11903 < N always — only c needs a check.
    if (bi != bj) {
#pragma unroll
        for (int j = 0; j < 8; j++) {
            int c = cbase + j;
            if (c < N_NODES) {
                float* orow = out + (size_t)c * N_NODES;
#pragma unroll
                for (int i4 = 0; i4 < 2; i4++) {
                    int r = rbase + i4 * 4;
                    *(float4*)(orow + r) = make_float4(acc[i4 * 4 + 0][j], acc[i4 * 4 + 1][j],
                                                       acc[i4 * 4 + 2][j], acc[i4 * 4 + 3][j]);
                }
            }
        }
    }
}

// ---------------- launch -----------------------------------------------------
extern "C" void kernel_launch(void* const* d_in, const int* in_sizes, int n_in,
                              void* d_out, int out_size) {
    const float* x     = (const float*)d_in[0];
    const int*   src   = (const int*)  d_in[1];
    const int*   dst   = (const int*)  d_in[2];
    const float* noise = (const float*)d_in[4];
    const float* W0  = (const float*)d_in[5];
    const float* b0  = (const float*)d_in[6];
    const float* g0  = (const float*)d_in[7];
    const float* be0 = (const float*)d_in[8];
    const float* Wm  = (const float*)d_in[9];
    const float* bm  = (const float*)d_in[10];
    const float* gm  = (const float*)d_in[11];
    const float* bem = (const float*)d_in[12];
    const float* Ws  = (const float*)d_in[13];
    const float* bs  = (const float*)d_in[14];
    const float* gs  = (const float*)d_in[15];
    const float* bes = (const float*)d_in[16];
    const float* Dw1 = (const float*)d_in[17];
    const float* Db1 = (const float*)d_in[18];
    const float* Dw2 = (const float*)d_in[19];
    const float* Db2 = (const float*)d_in[20];
    float* out = (float*)d_out;

    float* fsc; int* isc; double* sums;
    cudaGetSymbolAddress((void**)&fsc, g_fsc);
    cudaGetSymbolAddress((void**)&isc, g_isc);
    cudaGetSymbolAddress((void**)&sums, g_sums);

    float* HS   = fsc + 0 * BUF;
    float* SB   = fsc + 1 * BUF;
    float* HID  = fsc + 2 * BUF;
    float* MEAN = fsc + 3 * BUF;
    float* LOG  = fsc + 4 * BUF;
    float* Z    = fsc + 5 * BUF;
    float* H1   = fsc + 6 * BUF;
    float* DIS  = fsc + 7 * BUF;
    int* CNT = isc;
    int* OFF = CNT + N_NODES;
    int* CUR = OFF + N_NODES + 1;
    int* CSR = CUR + N_NODES;

    cudaFuncSetAttribute(apred_kernel, cudaFuncAttributeMaxDynamicSharedMemorySize, 65536);

    // graph prep
    zero_cnt_kernel<<<47, 256>>>(CNT);
    hist_kernel<<<1500, 256>>>(dst, CNT);
    scan_kernel<<<1, 1024>>>(CNT, OFF, CUR, DIS);
    fill_kernel<<<1500, 256>>>(src, dst, CUR, CSR);

    // layer 1: x(128) -> hidden(64)
    gemm_kernel<FIN_, DD, 0><<<750, 256>>>(x, W0, DIS, HS);
    gather_sig_kernel<<<1500, 256>>>(HS, DIS, OFF, CSR, b0, SB);
    zero_stats_kernel<<<1, 128>>>(sums);
    stats_kernel<<<64, 256>>>(SB, sums);
    bn_apply_kernel<<<3000, 256>>>(SB, sums, g0, be0, HID);

    // layer 2: hidden -> mean
    gemm_kernel<DD, DD, 0><<<750, 256>>>(HID, Wm, DIS, HS);
    gather_sig_kernel<<<1500, 256>>>(HS, DIS, OFF, CSR, bm, SB);
    zero_stats_kernel<<<1, 128>>>(sums);
    stats_kernel<<<64, 256>>>(SB, sums);
    bn_apply_kernel<<<3000, 256>>>(SB, sums, gm, bem, MEAN);

    // layer 3: hidden -> logstd
    gemm_kernel<DD, DD, 0><<<750, 256>>>(HID, Ws, DIS, HS);
    gather_sig_kernel<<<1500, 256>>>(HS, DIS, OFF, CSR, bs, SB);
    zero_stats_kernel<<<1, 128>>>(sums);
    stats_kernel<<<64, 256>>>(SB, sums);
    bn_apply_kernel<<<3000, 256>>>(SB, sums, gs, bes, LOG);

    // reparameterize
    z_kernel<<<3000, 256>>>(noise, LOG, MEAN, Z);

    // decoder MLP -> out[0 : 12000*128]
    gemm_kernel<DD, DD, 1><<<750, 256>>>(Z, Dw1, Db1, H1);
    gemm_kernel<DD, FIN_, 2><<<750, 256>>>(H1, Dw2, Db2, out);

    // A_pred -> out[12000*128 : ]  (symmetric: upper-tri blocks compute, write both)
    dim3 grid((N_NODES + 127) / 128, (N_NODES + 127) / 128);
    apred_kernel<<<grid, 256, 65536>>>(Z, out + (size_t)N_NODES * FIN_);
}

// round 4
// speedup vs baseline: 3.0677x; 1.2068x over previous
#include <cuda_runtime.h>
#include <cuda_bf16.h>
#include <math.h>
#include <stdint.h>

#define N_NODES 12000
#define N_EDGES 384000
#define FIN_    128
#define DD      64
#define BUF     (N_NODES * DD)   // 768000

// Scratch (no allocation allowed)
__device__ float  g_fsc[7 * BUF + N_NODES];
__device__ int    g_isc[N_NODES + (N_NODES + 1) + N_NODES + N_EDGES];
__device__ double g_sums[128];

// ---------------- graph prep ----------------
__global__ void zero_cnt_kernel(int* cnt) {
    int i = blockIdx.x * 256 + threadIdx.x;
    if (i < N_NODES) cnt[i] = 0;
}

__global__ void hist_kernel(const int* __restrict__ dst, int* cnt) {
    int i = blockIdx.x * 256 + threadIdx.x;
    atomicAdd(&cnt[dst[i]], 1);
}

__global__ void scan_kernel(const int* __restrict__ cnt, int* __restrict__ off,
                            int* __restrict__ cur, float* __restrict__ dis) {
    __shared__ int part[1024];
    const int C = 12;
    int tid = threadIdx.x;
    int base = tid * C;
    int loc[C];
    int s = 0;
#pragma unroll
    for (int j = 0; j < C; j++) {
        int i = base + j;
        int v = (i < N_NODES) ? cnt[i] : 0;
        loc[j] = v; s += v;
    }
    part[tid] = s;
    __syncthreads();
    for (int d = 1; d < 1024; d <<= 1) {
        int v = 0;
        if (tid >= d) v = part[tid - d];
        __syncthreads();
        part[tid] += v;
        __syncthreads();
    }
    int run = (tid == 0) ? 0 : part[tid - 1];
#pragma unroll
    for (int j = 0; j < C; j++) {
        int i = base + j;
        if (i < N_NODES) {
            off[i] = run; cur[i] = run;
            dis[i] = rsqrtf((float)(loc[j] + 1));
            run += loc[j];
        }
    }
    if (tid == 1023) off[N_NODES] = run;
}

__global__ void fill_kernel(const int* __restrict__ src, const int* __restrict__ dst,
                            int* cur, int* __restrict__ csr) {
    int i = blockIdx.x * 256 + threadIdx.x;
    int p = atomicAdd(&cur[dst[i]], 1);
    csr[p] = src[i];
}

// ---------------- small GEMM ----------------
template <int FIN, int NOUT, int EPI>
__global__ void gemm_kernel(const float* __restrict__ X, const float* __restrict__ W,
                            const float* __restrict__ aux, float* __restrict__ Y) {
    __shared__ float xs[16 * FIN];
    int tid = threadIdx.x;
    int rowbase = blockIdx.x * 16;
    const float4* Xg = (const float4*)(X + (size_t)rowbase * FIN);
    float4* xs4 = (float4*)xs;
#pragma unroll
    for (int u = tid; u < 16 * FIN / 4; u += 256) xs4[u] = Xg[u];
    __syncthreads();

    const int LANES = 256 / NOUT;
    const int RPT   = 16 / LANES;
    int col = tid % NOUT;
    int rl  = tid / NOUT;
    float acc[RPT];
#pragma unroll
    for (int r = 0; r < RPT; r++) acc[r] = 0.f;

#pragma unroll 4
    for (int k = 0; k < FIN; k++) {
        float w = __ldg(&W[k * NOUT + col]);
#pragma unroll
        for (int r = 0; r < RPT; r++)
            acc[r] += xs[(rl * RPT + r) * FIN + k] * w;
    }
#pragma unroll
    for (int r = 0; r < RPT; r++) {
        int row = rowbase + rl * RPT + r;
        float v = acc[r];
        if (EPI == 0) {
            v *= aux[row];
        } else {
            v += aux[col];
            if (EPI == 1) v = (v > 0.f) ? v : 0.01f * v;
        }
        Y[(size_t)row * NOUT + col] = v;
    }
}

// ------------- gather + bias + sigmoid ---------------
__global__ void gather_sig_kernel(const float* __restrict__ hs, const float* __restrict__ dis,
                                  const int* __restrict__ off, const int* __restrict__ csr,
                                  const float* __restrict__ bias, float* __restrict__ sbuf) {
    int warp = (blockIdx.x * 256 + threadIdx.x) >> 5;
    int lane = threadIdx.x & 31;
    const float2* h2 = (const float2*)hs;
    float2 acc = h2[(size_t)warp * 32 + lane];
    int e0 = off[warp], e1 = off[warp + 1];
    for (int e = e0; e < e1; e++) {
        int s = __ldg(&csr[e]);
        float2 v = h2[(size_t)s * 32 + lane];
        acc.x += v.x; acc.y += v.y;
    }
    float dd = dis[warp];
    float2 bb = ((const float2*)bias)[lane];
    float vx = dd * acc.x + bb.x;
    float vy = dd * acc.y + bb.y;
    vx = __fdividef(1.f, 1.f + __expf(-vx));
    vy = __fdividef(1.f, 1.f + __expf(-vy));
    ((float2*)sbuf)[(size_t)warp * 32 + lane] = make_float2(vx, vy);
}

// ---------------- BatchNorm ----------------
__global__ void zero_stats_kernel(double* sums) { sums[threadIdx.x] = 0.0; }

__global__ void stats_kernel(const float* __restrict__ sbuf, double* __restrict__ sums) {
    int tid = threadIdx.x;
    int c = tid & 63, rg = tid >> 6;
    double s = 0.0, s2 = 0.0;
    for (int row = blockIdx.x * 4 + rg; row < N_NODES; row += 64 * 4) {
        float v = sbuf[(size_t)row * 64 + c];
        s += v; s2 += (double)v * (double)v;
    }
    __shared__ double sh[256], sh2[256];
    sh[tid] = s; sh2[tid] = s2;
    __syncthreads();
    if (rg == 0) {
        s  = sh[tid]  + sh[tid + 64]  + sh[tid + 128]  + sh[tid + 192];
        s2 = sh2[tid] + sh2[tid + 64] + sh2[tid + 128] + sh2[tid + 192];
        atomicAdd(&sums[c], s);
        atomicAdd(&sums[64 + c], s2);
    }
}

__global__ void bn_apply_kernel(const float* __restrict__ sbuf, const double* __restrict__ sums,
                                const float* __restrict__ gamma, const float* __restrict__ beta,
                                float* __restrict__ out) {
    int idx = blockIdx.x * 256 + threadIdx.x;
    int c = idx & 63;
    double mu  = sums[c] * (1.0 / N_NODES);
    double var = sums[64 + c] * (1.0 / N_NODES) - mu * mu;
    float inv = rsqrtf((float)var + 1e-4f);
    out[idx] = (float)((double)sbuf[idx] - mu) * inv * gamma[c] + beta[c];
}

__global__ void z_kernel(const float* __restrict__ noise, const float* __restrict__ logstd,
                         const float* __restrict__ mean, float* __restrict__ z) {
    int idx = blockIdx.x * 256 + threadIdx.x;
    z[idx] = noise[idx] * expf(logstd[idx]) + mean[idx];
}

// ====== A_pred = sigmoid(z @ z^T) via mma.sync bf16 two-term split ==========
// D = Ahi*Bhi^T + Ahi*Blo^T + Alo*Bhi^T (fp32 accumulate). Per CTA 128x128
// tile, 8 warps in 4x2 (m x n), each warp 32x64 via m16n8k16 HMMA.
// Fragments loaded per the PTX ISA thread mapping as plain 32-bit LDS from
// 144B-pitch smem (conflict-free). Stores: float2 per quad-lane = 32B sectors.

#define TPITCH 72   // bf16 elements per smem row (144 bytes)

__device__ __forceinline__ void mma_bf16(float* c, const uint32_t* a, const uint32_t* b) {
    asm volatile(
        "mma.sync.aligned.m16n8k16.row.col.f32.bf16.bf16.f32 "
        "{%0,%1,%2,%3}, {%4,%5,%6,%7}, {%8,%9}, {%0,%1,%2,%3};"
        : "+f"(c[0]), "+f"(c[1]), "+f"(c[2]), "+f"(c[3])
        : "r"(a[0]), "r"(a[1]), "r"(a[2]), "r"(a[3]), "r"(b[0]), "r"(b[1]));
}

__global__ void __launch_bounds__(256, 2)
apred_mma_kernel(const float* __restrict__ z, float* __restrict__ out) {
    extern __shared__ __nv_bfloat16 sm[];
    __nv_bfloat16* Ahi = sm;
    __nv_bfloat16* Alo = sm + 128 * TPITCH;
    __nv_bfloat16* Bhi = sm + 2 * 128 * TPITCH;
    __nv_bfloat16* Blo = sm + 3 * 128 * TPITCH;

    int tid = threadIdx.x;
    int row0 = blockIdx.y * 128, col0 = blockIdx.x * 128;

    // ---- fill: split z rows into bf16 hi/lo ----
    for (int u = tid; u < 2048; u += 256) {
        int r = u >> 4, f4 = u & 15;            // f4: which float4 of the 64-wide row
        int gr = row0 + r;
        float4 v = make_float4(0.f, 0.f, 0.f, 0.f);
        if (gr < N_NODES) v = *(const float4*)(z + (size_t)gr * 64 + f4 * 4);
        {
            __nv_bfloat16 h0 = __float2bfloat16_rn(v.x), h1 = __float2bfloat16_rn(v.y);
            __nv_bfloat16 h2 = __float2bfloat16_rn(v.z), h3 = __float2bfloat16_rn(v.w);
            __nv_bfloat16 l0 = __float2bfloat16_rn(v.x - __bfloat162float(h0));
            __nv_bfloat16 l1 = __float2bfloat16_rn(v.y - __bfloat162float(h1));
            __nv_bfloat16 l2 = __float2bfloat16_rn(v.z - __bfloat162float(h2));
            __nv_bfloat16 l3 = __float2bfloat16_rn(v.w - __bfloat162float(h3));
            int e = r * TPITCH + f4 * 4;
            *(uint32_t*)&Ahi[e]     = ((uint32_t)__bfloat16_as_ushort(h1) << 16) | __bfloat16_as_ushort(h0);
            *(uint32_t*)&Ahi[e + 2] = ((uint32_t)__bfloat16_as_ushort(h3) << 16) | __bfloat16_as_ushort(h2);
            *(uint32_t*)&Alo[e]     = ((uint32_t)__bfloat16_as_ushort(l1) << 16) | __bfloat16_as_ushort(l0);
            *(uint32_t*)&Alo[e + 2] = ((uint32_t)__bfloat16_as_ushort(l3) << 16) | __bfloat16_as_ushort(l2);
        }
        int gc = col0 + r;
        float4 w = make_float4(0.f, 0.f, 0.f, 0.f);
        if (gc < N_NODES) w = *(const float4*)(z + (size_t)gc * 64 + f4 * 4);
        {
            __nv_bfloat16 h0 = __float2bfloat16_rn(w.x), h1 = __float2bfloat16_rn(w.y);
            __nv_bfloat16 h2 = __float2bfloat16_rn(w.z), h3 = __float2bfloat16_rn(w.w);
            __nv_bfloat16 l0 = __float2bfloat16_rn(w.x - __bfloat162float(h0));
            __nv_bfloat16 l1 = __float2bfloat16_rn(w.y - __bfloat162float(h1));
            __nv_bfloat16 l2 = __float2bfloat16_rn(w.z - __bfloat162float(h2));
            __nv_bfloat16 l3 = __float2bfloat16_rn(w.w - __bfloat162float(h3));
            int e = r * TPITCH + f4 * 4;
            *(uint32_t*)&Bhi[e]     = ((uint32_t)__bfloat16_as_ushort(h1) << 16) | __bfloat16_as_ushort(h0);
            *(uint32_t*)&Bhi[e + 2] = ((uint32_t)__bfloat16_as_ushort(h3) << 16) | __bfloat16_as_ushort(h2);
            *(uint32_t*)&Blo[e]     = ((uint32_t)__bfloat16_as_ushort(l1) << 16) | __bfloat16_as_ushort(l0);
            *(uint32_t*)&Blo[e + 2] = ((uint32_t)__bfloat16_as_ushort(l3) << 16) | __bfloat16_as_ushort(l2);
        }
    }
    __syncthreads();

    int wid = tid >> 5, lane = tid & 31;
    int gid = lane >> 2, tig = lane & 3;        // groupID, thread-in-group
    int m0 = (wid & 3) * 32;                    // warp's 32-row block
    int n0 = (wid >> 2) * 64;                   // warp's 64-col block

    float acc[2][8][4];
#pragma unroll
    for (int h = 0; h < 2; h++)
#pragma unroll
        for (int nb = 0; nb < 8; nb++)
#pragma unroll
            for (int q = 0; q < 4; q++) acc[h][nb][q] = 0.f;

#pragma unroll
    for (int p = 0; p < 3; p++) {
        const __nv_bfloat16* Ap = (p == 2) ? Alo : Ahi;
        const __nv_bfloat16* Bp = (p == 1) ? Blo : Bhi;
#pragma unroll
        for (int ks = 0; ks < 4; ks++) {
            int k0 = ks * 16;
            uint32_t a[2][4];
#pragma unroll
            for (int h = 0; h < 2; h++) {
                int r = m0 + 16 * h + gid;
                int e = r * TPITCH + k0 + 2 * tig;
                a[h][0] = *(const uint32_t*)&Ap[e];
                a[h][1] = *(const uint32_t*)&Ap[e + 8 * TPITCH];
                a[h][2] = *(const uint32_t*)&Ap[e + 8];
                a[h][3] = *(const uint32_t*)&Ap[e + 8 * TPITCH + 8];
            }
#pragma unroll
            for (int nb = 0; nb < 8; nb++) {
                int nr = n0 + 8 * nb + gid;
                int e = nr * TPITCH + k0 + 2 * tig;
                uint32_t b[2];
                b[0] = *(const uint32_t*)&Bp[e];
                b[1] = *(const uint32_t*)&Bp[e + 8];
                mma_bf16(acc[0][nb], a[0], b);
                mma_bf16(acc[1][nb], a[1], b);
            }
        }
    }

    // ---- epilogue: sigmoid + guarded float2 stores (32B per quad) ----
#pragma unroll
    for (int h = 0; h < 2; h++) {
#pragma unroll
        for (int nb = 0; nb < 8; nb++) {
            float* q = acc[h][nb];
            int r0 = row0 + m0 + 16 * h + gid;
            int c  = col0 + n0 + 8 * nb + 2 * tig;
            if (c < N_NODES) {
                if (r0 < N_NODES) {
                    float2 v;
                    v.x = __fdividef(1.f, 1.f + __expf(-q[0]));
                    v.y = __fdividef(1.f, 1.f + __expf(-q[1]));
                    *(float2*)(out + (size_t)r0 * N_NODES + c) = v;
                }
                int r1 = r0 + 8;
                if (r1 < N_NODES) {
                    float2 v;
                    v.x = __fdividef(1.f, 1.f + __expf(-q[2]));
                    v.y = __fdividef(1.f, 1.f + __expf(-q[3]));
                    *(float2*)(out + (size_t)r1 * N_NODES + c) = v;
                }
            }
        }
    }
}

// ---------------- launch -----------------------------------------------------
extern "C" void kernel_launch(void* const* d_in, const int* in_sizes, int n_in,
                              void* d_out, int out_size) {
    const float* x     = (const float*)d_in[0];
    const int*   src   = (const int*)  d_in[1];
    const int*   dst   = (const int*)  d_in[2];
    const float* noise = (const float*)d_in[4];
    const float* W0  = (const float*)d_in[5];
    const float* b0  = (const float*)d_in[6];
    const float* g0  = (const float*)d_in[7];
    const float* be0 = (const float*)d_in[8];
    const float* Wm  = (const float*)d_in[9];
    const float* bm  = (const float*)d_in[10];
    const float* gm  = (const float*)d_in[11];
    const float* bem = (const float*)d_in[12];
    const float* Ws  = (const float*)d_in[13];
    const float* bs  = (const float*)d_in[14];
    const float* gs  = (const float*)d_in[15];
    const float* bes = (const float*)d_in[16];
    const float* Dw1 = (const float*)d_in[17];
    const float* Db1 = (const float*)d_in[18];
    const float* Dw2 = (const float*)d_in[19];
    const float* Db2 = (const float*)d_in[20];
    float* out = (float*)d_out;

    float* fsc; int* isc; double* sums;
    cudaGetSymbolAddress((void**)&fsc, g_fsc);
    cudaGetSymbolAddress((void**)&isc, g_isc);
    cudaGetSymbolAddress((void**)&sums, g_sums);

    float* HS   = fsc + 0 * BUF;
    float* SB   = fsc + 1 * BUF;
    float* HID  = fsc + 2 * BUF;
    float* MEAN = fsc + 3 * BUF;
    float* LOG  = fsc + 4 * BUF;
    float* Z    = fsc + 5 * BUF;
    float* H1   = fsc + 6 * BUF;
    float* DIS  = fsc + 7 * BUF;
    int* CNT = isc;
    int* OFF = CNT + N_NODES;
    int* CUR = OFF + N_NODES + 1;
    int* CSR = CUR + N_NODES;

    const int APRED_SMEM = 4 * 128 * TPITCH * 2;   // 73728 bytes
    cudaFuncSetAttribute(apred_mma_kernel, cudaFuncAttributeMaxDynamicSharedMemorySize, APRED_SMEM);

    // graph prep
    zero_cnt_kernel<<<47, 256>>>(CNT);
    hist_kernel<<<1500, 256>>>(dst, CNT);
    scan_kernel<<<1, 1024>>>(CNT, OFF, CUR, DIS);
    fill_kernel<<<1500, 256>>>(src, dst, CUR, CSR);

    // layer 1: x(128) -> hidden(64)
    gemm_kernel<FIN_, DD, 0><<<750, 256>>>(x, W0, DIS, HS);
    gather_sig_kernel<<<1500, 256>>>(HS, DIS, OFF, CSR, b0, SB);
    zero_stats_kernel<<<1, 128>>>(sums);
    stats_kernel<<<64, 256>>>(SB, sums);
    bn_apply_kernel<<<3000, 256>>>(SB, sums, g0, be0, HID);

    // layer 2: hidden -> mean
    gemm_kernel<DD, DD, 0><<<750, 256>>>(HID, Wm, DIS, HS);
    gather_sig_kernel<<<1500, 256>>>(HS, DIS, OFF, CSR, bm, SB);
    zero_stats_kernel<<<1, 128>>>(sums);
    stats_kernel<<<64, 256>>>(SB, sums);
    bn_apply_kernel<<<3000, 256>>>(SB, sums, gm, bem, MEAN);

    // layer 3: hidden -> logstd
    gemm_kernel<DD, DD, 0><<<750, 256>>>(HID, Ws, DIS, HS);
    gather_sig_kernel<<<1500, 256>>>(HS, DIS, OFF, CSR, bs, SB);
    zero_stats_kernel<<<1, 128>>>(sums);
    stats_kernel<<<64, 256>>>(SB, sums);
    bn_apply_kernel<<<3000, 256>>>(SB, sums, gs, bes, LOG);

    // reparameterize
    z_kernel<<<3000, 256>>>(noise, LOG, MEAN, Z);

    // decoder MLP -> out[0 : 12000*128]
    gemm_kernel<DD, DD, 1><<<750, 256>>>(Z, Dw1, Db1, H1);
    gemm_kernel<DD, FIN_, 2><<<750, 256>>>(H1, Dw2, Db2, out);

    // A_pred -> out[12000*128 : ]  — mma.sync bf16 split path
    dim3 grid((N_NODES + 127) / 128, (N_NODES + 127) / 128);
    apred_mma_kernel<<<grid, 256, APRED_SMEM>>>(Z, out + (size_t)N_NODES * FIN_);
}